// round 12
// baseline (speedup 1.0000x reference)
#include <cuda_runtime.h>
#include <cuda_fp16.h>
#include <cstdint>

#define N_TOK 8192
#define DMODEL 1024
#define HDIM 4096
#define NEXP 8
#define LN_EPS 1e-5f
#define TOTALR (N_TOK * 2)

#define TILE_M 128
#define TILE_N 128
#define BK 64
#define STAGES 3
#define A_BYTES 16384           /* 128 rows * 128 B */
#define STAGE_BYTES 32768       /* A 16KB + B 16KB */
#define SMEM_DYN (STAGES * STAGE_BYTES)   /* 98304 */
#define MAX_TILES 136

// ---------------- scratch ----------------
__device__ __half g_w1h[(size_t)NEXP * HDIM * DMODEL];
__device__ __half g_w2h[(size_t)NEXP * DMODEL * HDIM];
__device__ __half g_xh[(size_t)N_TOK * DMODEL];
__device__ __half g_h16[(size_t)TOTALR * HDIM];
__device__ float  g_ybuf[(size_t)TOTALR * DMODEL];
__device__ int    g_topk_idx[TOTALR];
__device__ float  g_topk_w[TOTALR];
__device__ int    g_count[NEXP];
__device__ int    g_offset[NEXP];
__device__ int    g_cursor[NEXP];
__device__ int    g_list_token[TOTALR];
__device__ float  g_list_w[TOTALR];
__device__ int    g_pos[TOTALR];
__device__ int    g_tile_rbase[MAX_TILES];
__device__ int    g_tile_rows[MAX_TILES];
__device__ int    g_tile_e[MAX_TILES];
__device__ int    g_n_tiles;

// ---------------- PTX helpers ----------------
__device__ __forceinline__ uint32_t smem_u32(const void* p) {
    uint32_t a;
    asm("{ .reg .u64 t; cvta.to.shared.u64 t, %1; cvt.u32.u64 %0, t; }" : "=r"(a) : "l"(p));
    return a;
}

#define CP_ASYNC16(dst, src) \
    asm volatile("cp.async.cg.shared.global [%0], [%1], 16;" :: "r"((uint32_t)(dst)), "l"(src) : "memory")
#define CP_COMMIT() asm volatile("cp.async.commit_group;" ::: "memory")
#define CP_WAIT(n)  asm volatile("cp.async.wait_group %0;" :: "n"(n) : "memory")

#define LDSM_X4(r0, r1, r2, r3, addr) \
    asm volatile("ldmatrix.sync.aligned.m8n8.x4.shared.b16 {%0,%1,%2,%3}, [%4];" \
        : "=r"(r0), "=r"(r1), "=r"(r2), "=r"(r3) : "r"(addr))

#define MMA16816(c, a0, a1, a2, a3, b0, b1) \
    asm volatile("mma.sync.aligned.m16n8k16.row.col.f32.f16.f16.f32 " \
        "{%0,%1,%2,%3}, {%4,%5,%6,%7}, {%8,%9}, {%0,%1,%2,%3};" \
        : "+f"((c)[0]), "+f"((c)[1]), "+f"((c)[2]), "+f"((c)[3]) \
        : "r"(a0), "r"(a1), "r"(a2), "r"(a3), "r"(b0), "r"(b1))

// ---------------- weight convert (one tensor) ----------------
__global__ void cvtw_kernel(const float* __restrict__ src, __half* __restrict__ dst) {
    const int n8 = NEXP * HDIM * DMODEL / 8;
    int i = blockIdx.x * blockDim.x + threadIdx.x;
    int nth = gridDim.x * blockDim.x;
    for (; i < n8; i += nth) {
        float4 v0 = ((const float4*)src)[2 * i];
        float4 v1 = ((const float4*)src)[2 * i + 1];
        __align__(16) __half2 o[4];
        o[0] = __floats2half2_rn(v0.x, v0.y);
        o[1] = __floats2half2_rn(v0.z, v0.w);
        o[2] = __floats2half2_rn(v1.x, v1.y);
        o[3] = __floats2half2_rn(v1.z, v1.w);
        ((uint4*)dst)[i] = *(const uint4*)o;
    }
}

// ---------------- routing init ----------------
__global__ void init_kernel() {
    if (threadIdx.x < NEXP) { g_count[threadIdx.x] = 0; g_cursor[threadIdx.x] = 0; }
}

// ---------------- gating + x->fp16 ----------------
__global__ void gate_kernel(const float* __restrict__ x, const float* __restrict__ gw,
                            const float* __restrict__ gb) {
    __shared__ float xs[DMODEL];
    __shared__ float lg[NEXP];
    int n = blockIdx.x, tid = threadIdx.x;
    float4 xv = ((const float4*)(x + (size_t)n * DMODEL))[tid];
    ((float4*)xs)[tid] = xv;
    __half2* xo = (__half2*)(g_xh + (size_t)n * DMODEL) + 2 * tid;
    xo[0] = __floats2half2_rn(xv.x, xv.y);
    xo[1] = __floats2half2_rn(xv.z, xv.w);
    __syncthreads();
    int w = tid >> 5, lane = tid & 31;
    const float* gr = gw + w * DMODEL;
    float s = 0.f;
    #pragma unroll 8
    for (int j = lane; j < DMODEL; j += 32) s += xs[j] * gr[j];
    #pragma unroll
    for (int o = 16; o; o >>= 1) s += __shfl_xor_sync(0xffffffffu, s, o);
    if (lane == 0) lg[w] = s + gb[w];
    __syncthreads();
    if (tid == 0) {
        float l[NEXP];
        #pragma unroll
        for (int e = 0; e < NEXP; e++) l[e] = lg[e];
        int i1 = 0;
        #pragma unroll
        for (int e = 1; e < NEXP; e++) if (l[e] > l[i1]) i1 = e;
        int i2 = (i1 == 0) ? 1 : 0;
        #pragma unroll
        for (int e = 0; e < NEXP; e++) if (e != i1 && l[e] > l[i2]) i2 = e;
        float m = l[0];
        #pragma unroll
        for (int e = 1; e < NEXP; e++) m = fmaxf(m, l[e]);
        float z = 0.f;
        #pragma unroll
        for (int e = 0; e < NEXP; e++) z += expf(l[e] - m);
        float p1 = expf(l[i1] - m) / z;
        float p2 = expf(l[i2] - m) / z;
        float t = expf(p2 - p1);
        g_topk_idx[n * 2 + 0] = i1;
        g_topk_idx[n * 2 + 1] = i2;
        g_topk_w[n * 2 + 0] = 1.f / (1.f + t);
        g_topk_w[n * 2 + 1] = t / (1.f + t);
        atomicAdd(&g_count[i1], 1);
        atomicAdd(&g_count[i2], 1);
    }
}

// ---------------- scan + tile table + scatter ----------------
__global__ void scanscatter_kernel() {
    int tid = threadIdx.x;
    if (tid == 0) {
        int s = 0, nt = 0;
        for (int e = 0; e < NEXP; e++) {
            g_offset[e] = s;
            int c = g_count[e];
            for (int i = 0; i < c; i += TILE_M) {
                g_tile_rbase[nt] = s + i;
                g_tile_rows[nt] = min(c - i, TILE_M);
                g_tile_e[nt] = e;
                nt++;
            }
            s += c;
        }
        g_n_tiles = nt;
    }
    __syncthreads();
    for (int n = tid; n < N_TOK; n += blockDim.x) {
        #pragma unroll
        for (int s = 0; s < 2; s++) {
            int e = g_topk_idx[n * 2 + s];
            int pos = atomicAdd(&g_cursor[e], 1);
            int row = g_offset[e] + pos;
            g_list_token[row] = n;
            g_list_w[row] = g_topk_w[n * 2 + s];
            g_pos[n * 2 + s] = row;
        }
    }
}

// ---------------- persistent fp16 mma.sync grouped GEMM ----------------
template <int KD, int NOUT, int PHASE>
__global__ __launch_bounds__(256, 2)
void ffn_kernel(const __half* __restrict__ W, const float* __restrict__ bias) {
    constexpr int T = KD / BK;
    constexpr int NY = NOUT / TILE_N;

    extern __shared__ __align__(1024) char smem[];
    uint32_t sbase = smem_u32(smem);

    int tid = threadIdx.x;
    int lane = tid & 31, wid = tid >> 5;
    int warp_m = wid & 1;          // 2 x 64 rows
    int warp_n = wid >> 1;         // 4 x 32 cols

    int c8 = tid & 7;
    int rsub = tid >> 3;          // 0..31
    uint32_t pdst0 = (uint32_t)(rsub * 128 + ((c8 ^ (rsub & 7)) << 4));

    // ldmatrix address precompute (item-invariant)
    int a_row = warp_m * 64 + (lane & 15);
    int a_hi = (lane >> 4) & 1;
    int a_x = a_row & 7;
    uint32_t a_off = (uint32_t)(a_row * 128);
    int b_row = warp_n * 32 + (lane & 7) + ((lane & 16) ? 8 : 0);
    int b_hi = (lane >> 3) & 1;
    int b_x = b_row & 7;
    uint32_t b_off = (uint32_t)(A_BYTES + b_row * 128);

    int n_items = g_n_tiles * NY;

    for (int item = blockIdx.x; item < n_items; item += gridDim.x) {
        int tile = item / NY;
        int nbase = (item % NY) * TILE_N;   // ny fastest -> concurrent CTAs share A tiles
        int e = g_tile_e[tile];
        int rbase = g_tile_rbase[tile];
        int nrows = g_tile_rows[tile];

        const char* asrc[4];
        if (PHASE == 1) {
            #pragma unroll
            for (int j = 0; j < 4; j++) {
                int rl = 32 * j + rsub;
                if (rl >= nrows) rl = nrows - 1;
                asrc[j] = (const char*)(g_xh + (size_t)g_list_token[rbase + rl] * DMODEL) + c8 * 16;
            }
        } else {
            const char* a0 = (const char*)(g_h16 + (size_t)(rbase + rsub) * HDIM) + c8 * 16;
            #pragma unroll
            for (int j = 0; j < 4; j++)
                asrc[j] = a0 + (size_t)(32 * j) * HDIM * sizeof(__half);
        }
        const char* bsrc = (const char*)(W + ((size_t)e * NOUT + nbase + rsub) * KD) + c8 * 16;

        auto issue_tile = [&](int t) {
            uint32_t sb = sbase + (t % STAGES) * STAGE_BYTES;
            size_t koff = (size_t)t * 128;
            #pragma unroll
            for (int j = 0; j < 4; j++)
                CP_ASYNC16(sb + pdst0 + j * 4096, asrc[j] + koff);
            #pragma unroll
            for (int j = 0; j < 4; j++)
                CP_ASYNC16(sb + A_BYTES + pdst0 + j * 4096,
                           bsrc + koff + (size_t)j * 32 * KD * sizeof(__half));
        };

        float acc[4][4][4];
        #pragma unroll
        for (int mi = 0; mi < 4; mi++)
            #pragma unroll
            for (int ni = 0; ni < 4; ni++)
                #pragma unroll
                for (int q = 0; q < 4; q++) acc[mi][ni][q] = 0.f;

        // all warps must be done READING the previous item's stages before refill
        __syncthreads();

        issue_tile(0); CP_COMMIT();
        issue_tile(1); CP_COMMIT();

        for (int t = 0; t < T; t++) {
            CP_WAIT(1);
            __syncthreads();
            if (t + 2 < T) issue_tile(t + 2);
            CP_COMMIT();

            uint32_t sb = sbase + (t % STAGES) * STAGE_BYTES;
            #pragma unroll
            for (int g = 0; g < 4; g++) {
                uint32_t ach = (uint32_t)(((2 * g + a_hi) ^ a_x) << 4);
                uint32_t bch = (uint32_t)(((2 * g + b_hi) ^ b_x) << 4);
                uint32_t a[4][4], b[2][4];
                #pragma unroll
                for (int mi = 0; mi < 4; mi++)
                    LDSM_X4(a[mi][0], a[mi][1], a[mi][2], a[mi][3],
                            sb + a_off + mi * 2048 + ach);
                #pragma unroll
                for (int ni = 0; ni < 2; ni++)
                    LDSM_X4(b[ni][0], b[ni][1], b[ni][2], b[ni][3],
                            sb + b_off + ni * 2048 + bch);
                #pragma unroll
                for (int mi = 0; mi < 4; mi++)
                    #pragma unroll
                    for (int ni = 0; ni < 2; ni++) {
                        MMA16816(acc[mi][2 * ni],     a[mi][0], a[mi][1], a[mi][2], a[mi][3],
                                 b[ni][0], b[ni][1]);
                        MMA16816(acc[mi][2 * ni + 1], a[mi][0], a[mi][1], a[mi][2], a[mi][3],
                                 b[ni][2], b[ni][3]);
                    }
            }
        }

        int r0 = warp_m * 64 + (lane >> 2);
        int cql = (lane & 3) * 2;
        #pragma unroll
        for (int mi = 0; mi < 4; mi++) {
            #pragma unroll
            for (int half = 0; half < 2; half++) {
                int r = r0 + mi * 16 + half * 8;
                if (r < nrows) {
                    int rglob = rbase + r;
                    if (PHASE == 1) {
                        __half* hp = g_h16 + (size_t)rglob * HDIM + nbase + warp_n * 32 + cql;
                        const float* bp = bias + (size_t)e * NOUT + nbase + warp_n * 32 + cql;
                        #pragma unroll
                        for (int n8 = 0; n8 < 4; n8++) {
                            float v0 = fmaxf(acc[mi][n8][half * 2 + 0] + bp[n8 * 8], 0.f);
                            float v1 = fmaxf(acc[mi][n8][half * 2 + 1] + bp[n8 * 8 + 1], 0.f);
                            *(__half2*)(hp + n8 * 8) = __floats2half2_rn(v0, v1);
                        }
                    } else {
                        float wgt = g_list_w[rglob];
                        float* yp = g_ybuf + (size_t)rglob * DMODEL + nbase + warp_n * 32 + cql;
                        const float* bp = bias + (size_t)e * NOUT + nbase + warp_n * 32 + cql;
                        #pragma unroll
                        for (int n8 = 0; n8 < 4; n8++) {
                            float v0 = (acc[mi][n8][half * 2 + 0] + bp[n8 * 8]) * wgt;
                            float v1 = (acc[mi][n8][half * 2 + 1] + bp[n8 * 8 + 1]) * wgt;
                            *(float2*)(yp + n8 * 8) = make_float2(v0, v1);
                        }
                    }
                }
            }
        }
    }
}

// ---------------- residual + LayerNorm ----------------
__device__ __forceinline__ float block_sum(float v, float* red) {
    __syncthreads();
    #pragma unroll
    for (int o = 16; o; o >>= 1) v += __shfl_xor_sync(0xffffffffu, v, o);
    int w = threadIdx.x >> 5, lane = threadIdx.x & 31;
    if (lane == 0) red[w] = v;
    __syncthreads();
    if (w == 0) {
        v = (lane < 8) ? red[lane] : 0.f;
        #pragma unroll
        for (int o = 4; o; o >>= 1) v += __shfl_xor_sync(0xffffffffu, v, o);
        if (lane == 0) red[0] = v;
    }
    __syncthreads();
    return red[0];
}

__global__ void ln_kernel(const float* __restrict__ x, const float* __restrict__ lnw,
                          const float* __restrict__ lnb, float* __restrict__ out) {
    __shared__ float red[32];
    int n = blockIdx.x, tid = threadIdx.x;
    int p0 = g_pos[n * 2 + 0];
    int p1 = g_pos[n * 2 + 1];
    float4 xv = ((const float4*)(x + (size_t)n * DMODEL))[tid];
    float4 a0 = ((const float4*)(&g_ybuf[(size_t)p0 * DMODEL]))[tid];
    float4 a1 = ((const float4*)(&g_ybuf[(size_t)p1 * DMODEL]))[tid];
    float rx = xv.x + a0.x + a1.x, ry = xv.y + a0.y + a1.y;
    float rz = xv.z + a0.z + a1.z, rw = xv.w + a0.w + a1.w;
    float s = block_sum(rx + ry + rz + rw, red);
    float mu = s * (1.f / DMODEL);
    float dx = rx - mu, dy = ry - mu, dz = rz - mu, dw = rw - mu;
    float sq = block_sum(dx * dx + dy * dy + dz * dz + dw * dw, red);
    float inv = rsqrtf(sq * (1.f / DMODEL) + LN_EPS);
    float4 wv = ((const float4*)lnw)[tid];
    float4 bv = ((const float4*)lnb)[tid];
    float4 o = make_float4(dx * inv * wv.x + bv.x, dy * inv * wv.y + bv.y,
                           dz * inv * wv.z + bv.z, dw * inv * wv.w + bv.w);
    ((float4*)(out + (size_t)n * DMODEL))[tid] = o;
}

// ---------------- launch: stream-forked graph + persistent GEMMs ----------------
extern "C" void kernel_launch(void* const* d_in, const int* in_sizes, int n_in,
                              void* d_out, int out_size) {
    const float* x   = (const float*)d_in[0];
    const float* gw  = (const float*)d_in[1];
    const float* gb  = (const float*)d_in[2];
    const float* w1  = (const float*)d_in[3];
    const float* b1  = (const float*)d_in[4];
    const float* w2  = (const float*)d_in[5];
    const float* b2  = (const float*)d_in[6];
    const float* lnw = (const float*)d_in[7];
    const float* lnb = (const float*)d_in[8];
    float* out = (float*)d_out;

    __half* w1h; cudaGetSymbolAddress((void**)&w1h, g_w1h);
    __half* w2h; cudaGetSymbolAddress((void**)&w2h, g_w2h);

    cudaFuncSetAttribute(ffn_kernel<DMODEL, HDIM, 1>,
                         cudaFuncAttributeMaxDynamicSharedMemorySize, SMEM_DYN);
    cudaFuncSetAttribute(ffn_kernel<HDIM, DMODEL, 2>,
                         cudaFuncAttributeMaxDynamicSharedMemorySize, SMEM_DYN);

    static cudaStream_t s1 = nullptr, s2 = nullptr;
    static cudaEvent_t ev0 = nullptr, evA = nullptr, evB = nullptr, evC = nullptr;
    static int nsm = 0;
    if (!s1) {
        cudaStreamCreateWithFlags(&s1, cudaStreamNonBlocking);
        cudaStreamCreateWithFlags(&s2, cudaStreamNonBlocking);
        cudaEventCreateWithFlags(&ev0, cudaEventDisableTiming);
        cudaEventCreateWithFlags(&evA, cudaEventDisableTiming);
        cudaEventCreateWithFlags(&evB, cudaEventDisableTiming);
        cudaEventCreateWithFlags(&evC, cudaEventDisableTiming);
        cudaDeviceProp prop;
        cudaGetDeviceProperties(&prop, 0);
        nsm = prop.multiProcessorCount;
    }
    int pgrid = 2 * nsm;   // 2 CTAs/SM resident -> exactly one wave

    // fork s1 (routing path)
    cudaEventRecord(ev0, 0);
    cudaStreamWaitEvent(s1, ev0, 0);
    init_kernel<<<1, 32, 0, s1>>>();
    gate_kernel<<<N_TOK, 256, 0, s1>>>(x, gw, gb);
    scanscatter_kernel<<<1, 1024, 0, s1>>>();
    cudaEventRecord(evA, s1);

    // default: convert w1 (critical path head)
    cvtw_kernel<<<4096, 256>>>(w1, w1h);
    cudaEventRecord(evC, 0);

    // s2: convert w2, concurrent with ffn1
    cudaStreamWaitEvent(s2, evC, 0);
    cvtw_kernel<<<4096, 256, 0, s2>>>(w2, w2h);
    cudaEventRecord(evB, s2);

    // default: persistent ffn1 after routing + w1h
    cudaStreamWaitEvent(0, evA, 0);
    ffn_kernel<DMODEL, HDIM, 1><<<pgrid, 256, SMEM_DYN>>>(w1h, b1);

    // default: persistent ffn2 after ffn1 + w2h
    cudaStreamWaitEvent(0, evB, 0);
    ffn_kernel<HDIM, DMODEL, 2><<<pgrid, 256, SMEM_DYN>>>(w2h, b2);

    ln_kernel<<<N_TOK, 256>>>(x, lnw, lnb, out);
}

// round 13
// speedup vs baseline: 1.1315x; 1.1315x over previous
#include <cuda_runtime.h>
#include <cuda_fp16.h>
#include <cstdint>

#define N_TOK 8192
#define DMODEL 1024
#define HDIM 4096
#define NEXP 8
#define LN_EPS 1e-5f
#define TOTALR (N_TOK * 2)

#define TILE_M 128
#define TILE_N 128
#define BK 64
#define STAGES 3
#define A_BYTES 16384           /* 128 rows * 128 B */
#define STAGE_BYTES 32768       /* A 16KB + B 16KB */
#define SMEM_DYN (STAGES * STAGE_BYTES)   /* 98304 */
#define MAX_TILES 136

// ---------------- scratch ----------------
__device__ __half g_w1h[(size_t)NEXP * HDIM * DMODEL];
__device__ __half g_w2h[(size_t)NEXP * DMODEL * HDIM];
__device__ __half g_xh[(size_t)N_TOK * DMODEL];
__device__ __half g_h16[(size_t)TOTALR * HDIM];
__device__ float  g_ybuf[(size_t)TOTALR * DMODEL];
__device__ int    g_topk_idx[TOTALR];
__device__ float  g_topk_w[TOTALR];
__device__ int    g_count[NEXP];
__device__ int    g_offset[NEXP];
__device__ int    g_cursor[NEXP];
__device__ int    g_list_token[TOTALR];
__device__ float  g_list_w[TOTALR];
__device__ int    g_pos[TOTALR];
__device__ int    g_tile_rbase[MAX_TILES];
__device__ int    g_tile_rows[MAX_TILES];
__device__ int    g_tile_e[MAX_TILES];
__device__ int    g_n_tiles;

// ---------------- PTX helpers ----------------
__device__ __forceinline__ uint32_t smem_u32(const void* p) {
    uint32_t a;
    asm("{ .reg .u64 t; cvta.to.shared.u64 t, %1; cvt.u32.u64 %0, t; }" : "=r"(a) : "l"(p));
    return a;
}

#define CP_ASYNC16(dst, src) \
    asm volatile("cp.async.cg.shared.global [%0], [%1], 16;" :: "r"((uint32_t)(dst)), "l"(src) : "memory")
#define CP_COMMIT() asm volatile("cp.async.commit_group;" ::: "memory")
#define CP_WAIT(n)  asm volatile("cp.async.wait_group %0;" :: "n"(n) : "memory")

#define LDSM_X4(r0, r1, r2, r3, addr) \
    asm volatile("ldmatrix.sync.aligned.m8n8.x4.shared.b16 {%0,%1,%2,%3}, [%4];" \
        : "=r"(r0), "=r"(r1), "=r"(r2), "=r"(r3) : "r"(addr))

#define MMA16816(c, a0, a1, a2, a3, b0, b1) \
    asm volatile("mma.sync.aligned.m16n8k16.row.col.f32.f16.f16.f32 " \
        "{%0,%1,%2,%3}, {%4,%5,%6,%7}, {%8,%9}, {%0,%1,%2,%3};" \
        : "+f"((c)[0]), "+f"((c)[1]), "+f"((c)[2]), "+f"((c)[3]) \
        : "r"(a0), "r"(a1), "r"(a2), "r"(a3), "r"(b0), "r"(b1))

// ---------------- weight convert (one tensor) ----------------
__global__ void cvtw_kernel(const float* __restrict__ src, __half* __restrict__ dst) {
    const int n8 = NEXP * HDIM * DMODEL / 8;
    int i = blockIdx.x * blockDim.x + threadIdx.x;
    int nth = gridDim.x * blockDim.x;
    for (; i < n8; i += nth) {
        float4 v0 = ((const float4*)src)[2 * i];
        float4 v1 = ((const float4*)src)[2 * i + 1];
        __align__(16) __half2 o[4];
        o[0] = __floats2half2_rn(v0.x, v0.y);
        o[1] = __floats2half2_rn(v0.z, v0.w);
        o[2] = __floats2half2_rn(v1.x, v1.y);
        o[3] = __floats2half2_rn(v1.z, v1.w);
        ((uint4*)dst)[i] = *(const uint4*)o;
    }
}

// ---------------- routing init ----------------
__global__ void init_kernel() {
    if (threadIdx.x < NEXP) { g_count[threadIdx.x] = 0; g_cursor[threadIdx.x] = 0; }
}

// ---------------- gating + x->fp16 ----------------
__global__ void gate_kernel(const float* __restrict__ x, const float* __restrict__ gw,
                            const float* __restrict__ gb) {
    __shared__ float xs[DMODEL];
    __shared__ float lg[NEXP];
    int n = blockIdx.x, tid = threadIdx.x;
    float4 xv = ((const float4*)(x + (size_t)n * DMODEL))[tid];
    ((float4*)xs)[tid] = xv;
    __half2* xo = (__half2*)(g_xh + (size_t)n * DMODEL) + 2 * tid;
    xo[0] = __floats2half2_rn(xv.x, xv.y);
    xo[1] = __floats2half2_rn(xv.z, xv.w);
    __syncthreads();
    int w = tid >> 5, lane = tid & 31;
    const float* gr = gw + w * DMODEL;
    float s = 0.f;
    #pragma unroll 8
    for (int j = lane; j < DMODEL; j += 32) s += xs[j] * gr[j];
    #pragma unroll
    for (int o = 16; o; o >>= 1) s += __shfl_xor_sync(0xffffffffu, s, o);
    if (lane == 0) lg[w] = s + gb[w];
    __syncthreads();
    if (tid == 0) {
        float l[NEXP];
        #pragma unroll
        for (int e = 0; e < NEXP; e++) l[e] = lg[e];
        int i1 = 0;
        #pragma unroll
        for (int e = 1; e < NEXP; e++) if (l[e] > l[i1]) i1 = e;
        int i2 = (i1 == 0) ? 1 : 0;
        #pragma unroll
        for (int e = 0; e < NEXP; e++) if (e != i1 && l[e] > l[i2]) i2 = e;
        float m = l[0];
        #pragma unroll
        for (int e = 1; e < NEXP; e++) m = fmaxf(m, l[e]);
        float z = 0.f;
        #pragma unroll
        for (int e = 0; e < NEXP; e++) z += expf(l[e] - m);
        float p1 = expf(l[i1] - m) / z;
        float p2 = expf(l[i2] - m) / z;
        float t = expf(p2 - p1);
        g_topk_idx[n * 2 + 0] = i1;
        g_topk_idx[n * 2 + 1] = i2;
        g_topk_w[n * 2 + 0] = 1.f / (1.f + t);
        g_topk_w[n * 2 + 1] = t / (1.f + t);
        atomicAdd(&g_count[i1], 1);
        atomicAdd(&g_count[i2], 1);
    }
}

// ---------------- scan + tile table + scatter ----------------
__global__ void scanscatter_kernel() {
    int tid = threadIdx.x;
    if (tid == 0) {
        int s = 0, nt = 0;
        for (int e = 0; e < NEXP; e++) {
            g_offset[e] = s;
            int c = g_count[e];
            for (int i = 0; i < c; i += TILE_M) {
                g_tile_rbase[nt] = s + i;
                g_tile_rows[nt] = min(c - i, TILE_M);
                g_tile_e[nt] = e;
                nt++;
            }
            s += c;
        }
        g_n_tiles = nt;
    }
    __syncthreads();
    for (int n = tid; n < N_TOK; n += blockDim.x) {
        #pragma unroll
        for (int s = 0; s < 2; s++) {
            int e = g_topk_idx[n * 2 + s];
            int pos = atomicAdd(&g_cursor[e], 1);
            int row = g_offset[e] + pos;
            g_list_token[row] = n;
            g_list_w[row] = g_topk_w[n * 2 + s];
            g_pos[n * 2 + s] = row;
        }
    }
}

// ---------------- fp16 mma.sync grouped GEMM (R7/R11 config, spread cp.async) ----------------
template <int KD, int NOUT, int PHASE>
__global__ __launch_bounds__(256, 2)
void ffn_kernel(const __half* __restrict__ W, const float* __restrict__ bias) {
    int tile = blockIdx.y;
    if (tile >= g_n_tiles) return;
    int e = g_tile_e[tile];
    int rbase = g_tile_rbase[tile];
    int nrows = g_tile_rows[tile];
    int nbase = blockIdx.x * TILE_N;
    constexpr int T = KD / BK;

    extern __shared__ __align__(1024) char smem[];
    uint32_t sbase = smem_u32(smem);

    int tid = threadIdx.x;
    int lane = tid & 31, wid = tid >> 5;
    int warp_m = wid & 1;          // 2 x 64 rows
    int warp_n = wid >> 1;         // 4 x 32 cols

    int c8 = tid & 7;
    int rsub = tid >> 3;          // 0..31
    uint32_t pdst0 = (uint32_t)(rsub * 128 + ((c8 ^ (rsub & 7)) << 4));

    const char* asrc[4];
    if (PHASE == 1) {
        #pragma unroll
        for (int j = 0; j < 4; j++) {
            int rl = 32 * j + rsub;
            if (rl >= nrows) rl = nrows - 1;
            asrc[j] = (const char*)(g_xh + (size_t)g_list_token[rbase + rl] * DMODEL) + c8 * 16;
        }
    } else {
        const char* a0 = (const char*)(g_h16 + (size_t)(rbase + rsub) * HDIM) + c8 * 16;
        #pragma unroll
        for (int j = 0; j < 4; j++)
            asrc[j] = a0 + (size_t)(32 * j) * HDIM * sizeof(__half);
    }
    const char* bsrc = (const char*)(W + ((size_t)e * NOUT + nbase + rsub) * KD) + c8 * 16;

    auto issue_tile = [&](int t) {
        uint32_t sb = sbase + (t % STAGES) * STAGE_BYTES;
        size_t koff = (size_t)t * 128;
        #pragma unroll
        for (int j = 0; j < 4; j++)
            CP_ASYNC16(sb + pdst0 + j * 4096, asrc[j] + koff);
        #pragma unroll
        for (int j = 0; j < 4; j++)
            CP_ASYNC16(sb + A_BYTES + pdst0 + j * 4096,
                       bsrc + koff + (size_t)j * 32 * KD * sizeof(__half));
    };

    int a_row = warp_m * 64 + (lane & 15);
    int a_hi = (lane >> 4) & 1;
    int a_x = a_row & 7;
    uint32_t a_off = (uint32_t)(a_row * 128);
    int b_row = warp_n * 32 + (lane & 7) + ((lane & 16) ? 8 : 0);
    int b_hi = (lane >> 3) & 1;
    int b_x = b_row & 7;
    uint32_t b_off = (uint32_t)(A_BYTES + b_row * 128);

    float acc[4][4][4];
    #pragma unroll
    for (int mi = 0; mi < 4; mi++)
        #pragma unroll
        for (int ni = 0; ni < 4; ni++)
            #pragma unroll
            for (int q = 0; q < 4; q++) acc[mi][ni][q] = 0.f;

    issue_tile(0); CP_COMMIT();
    issue_tile(1); CP_COMMIT();

    for (int t = 0; t < T; t++) {
        CP_WAIT(1);
        __syncthreads();

        bool pf = (t + 2 < T);
        uint32_t sbw = sbase + ((t + 2) % STAGES) * STAGE_BYTES;
        size_t koff2 = (size_t)(t + 2) * 128;
        uint32_t sb = sbase + (t % STAGES) * STAGE_BYTES;

        #pragma unroll
        for (int g = 0; g < 4; g++) {
            uint32_t ach = (uint32_t)(((2 * g + a_hi) ^ a_x) << 4);
            uint32_t bch = (uint32_t)(((2 * g + b_hi) ^ b_x) << 4);
            uint32_t a[4][4], b[2][4];
            #pragma unroll
            for (int mi = 0; mi < 4; mi++)
                LDSM_X4(a[mi][0], a[mi][1], a[mi][2], a[mi][3],
                        sb + a_off + mi * 2048 + ach);
            #pragma unroll
            for (int ni = 0; ni < 2; ni++)
                LDSM_X4(b[ni][0], b[ni][1], b[ni][2], b[ni][3],
                        sb + b_off + ni * 2048 + bch);
            #pragma unroll
            for (int mi = 0; mi < 4; mi++)
                #pragma unroll
                for (int ni = 0; ni < 2; ni++) {
                    MMA16816(acc[mi][2 * ni],     a[mi][0], a[mi][1], a[mi][2], a[mi][3],
                             b[ni][0], b[ni][1]);
                    MMA16816(acc[mi][2 * ni + 1], a[mi][0], a[mi][1], a[mi][2], a[mi][3],
                             b[ni][2], b[ni][3]);
                }
            // spread next-tile prefetch: 2 cp.async per group, away from the
            // post-barrier LDSM ramp where the LSU is already saturated
            if (pf) {
                if (g < 2) {
                    CP_ASYNC16(sbw + pdst0 + (2 * g) * 4096,     asrc[2 * g] + koff2);
                    CP_ASYNC16(sbw + pdst0 + (2 * g + 1) * 4096, asrc[2 * g + 1] + koff2);
                } else {
                    int j0 = 2 * (g - 2);
                    CP_ASYNC16(sbw + A_BYTES + pdst0 + j0 * 4096,
                               bsrc + koff2 + (size_t)j0 * 32 * KD * sizeof(__half));
                    CP_ASYNC16(sbw + A_BYTES + pdst0 + (j0 + 1) * 4096,
                               bsrc + koff2 + (size_t)(j0 + 1) * 32 * KD * sizeof(__half));
                }
            }
        }
        CP_COMMIT();
    }

    int r0 = warp_m * 64 + (lane >> 2);
    int cql = (lane & 3) * 2;
    #pragma unroll
    for (int mi = 0; mi < 4; mi++) {
        #pragma unroll
        for (int half = 0; half < 2; half++) {
            int r = r0 + mi * 16 + half * 8;
            if (r < nrows) {
                int rglob = rbase + r;
                if (PHASE == 1) {
                    __half* hp = g_h16 + (size_t)rglob * HDIM + nbase + warp_n * 32 + cql;
                    const float* bp = bias + (size_t)e * NOUT + nbase + warp_n * 32 + cql;
                    #pragma unroll
                    for (int n8 = 0; n8 < 4; n8++) {
                        float v0 = fmaxf(acc[mi][n8][half * 2 + 0] + bp[n8 * 8], 0.f);
                        float v1 = fmaxf(acc[mi][n8][half * 2 + 1] + bp[n8 * 8 + 1], 0.f);
                        *(__half2*)(hp + n8 * 8) = __floats2half2_rn(v0, v1);
                    }
                } else {
                    float wgt = g_list_w[rglob];
                    float* yp = g_ybuf + (size_t)rglob * DMODEL + nbase + warp_n * 32 + cql;
                    const float* bp = bias + (size_t)e * NOUT + nbase + warp_n * 32 + cql;
                    #pragma unroll
                    for (int n8 = 0; n8 < 4; n8++) {
                        float v0 = (acc[mi][n8][half * 2 + 0] + bp[n8 * 8]) * wgt;
                        float v1 = (acc[mi][n8][half * 2 + 1] + bp[n8 * 8 + 1]) * wgt;
                        *(float2*)(yp + n8 * 8) = make_float2(v0, v1);
                    }
                }
            }
        }
    }
}

// ---------------- residual + LayerNorm ----------------
__device__ __forceinline__ float block_sum(float v, float* red) {
    __syncthreads();
    #pragma unroll
    for (int o = 16; o; o >>= 1) v += __shfl_xor_sync(0xffffffffu, v, o);
    int w = threadIdx.x >> 5, lane = threadIdx.x & 31;
    if (lane == 0) red[w] = v;
    __syncthreads();
    if (w == 0) {
        v = (lane < 8) ? red[lane] : 0.f;
        #pragma unroll
        for (int o = 4; o; o >>= 1) v += __shfl_xor_sync(0xffffffffu, v, o);
        if (lane == 0) red[0] = v;
    }
    __syncthreads();
    return red[0];
}

__global__ void ln_kernel(const float* __restrict__ x, const float* __restrict__ lnw,
                          const float* __restrict__ lnb, float* __restrict__ out) {
    __shared__ float red[32];
    int n = blockIdx.x, tid = threadIdx.x;
    int p0 = g_pos[n * 2 + 0];
    int p1 = g_pos[n * 2 + 1];
    float4 xv = ((const float4*)(x + (size_t)n * DMODEL))[tid];
    float4 a0 = ((const float4*)(&g_ybuf[(size_t)p0 * DMODEL]))[tid];
    float4 a1 = ((const float4*)(&g_ybuf[(size_t)p1 * DMODEL]))[tid];
    float rx = xv.x + a0.x + a1.x, ry = xv.y + a0.y + a1.y;
    float rz = xv.z + a0.z + a1.z, rw = xv.w + a0.w + a1.w;
    float s = block_sum(rx + ry + rz + rw, red);
    float mu = s * (1.f / DMODEL);
    float dx = rx - mu, dy = ry - mu, dz = rz - mu, dw = rw - mu;
    float sq = block_sum(dx * dx + dy * dy + dz * dz + dw * dw, red);
    float inv = rsqrtf(sq * (1.f / DMODEL) + LN_EPS);
    float4 wv = ((const float4*)lnw)[tid];
    float4 bv = ((const float4*)lnb)[tid];
    float4 o = make_float4(dx * inv * wv.x + bv.x, dy * inv * wv.y + bv.y,
                           dz * inv * wv.z + bv.z, dw * inv * wv.w + bv.w);
    ((float4*)(out + (size_t)n * DMODEL))[tid] = o;
}

// ---------------- launch: stream-forked graph ----------------
extern "C" void kernel_launch(void* const* d_in, const int* in_sizes, int n_in,
                              void* d_out, int out_size) {
    const float* x   = (const float*)d_in[0];
    const float* gw  = (const float*)d_in[1];
    const float* gb  = (const float*)d_in[2];
    const float* w1  = (const float*)d_in[3];
    const float* b1  = (const float*)d_in[4];
    const float* w2  = (const float*)d_in[5];
    const float* b2  = (const float*)d_in[6];
    const float* lnw = (const float*)d_in[7];
    const float* lnb = (const float*)d_in[8];
    float* out = (float*)d_out;

    __half* w1h; cudaGetSymbolAddress((void**)&w1h, g_w1h);
    __half* w2h; cudaGetSymbolAddress((void**)&w2h, g_w2h);

    cudaFuncSetAttribute(ffn_kernel<DMODEL, HDIM, 1>,
                         cudaFuncAttributeMaxDynamicSharedMemorySize, SMEM_DYN);
    cudaFuncSetAttribute(ffn_kernel<HDIM, DMODEL, 2>,
                         cudaFuncAttributeMaxDynamicSharedMemorySize, SMEM_DYN);

    static cudaStream_t s1 = nullptr, s2 = nullptr;
    static cudaEvent_t ev0 = nullptr, evA = nullptr, evB = nullptr, evC = nullptr;
    if (!s1) {
        cudaStreamCreateWithFlags(&s1, cudaStreamNonBlocking);
        cudaStreamCreateWithFlags(&s2, cudaStreamNonBlocking);
        cudaEventCreateWithFlags(&ev0, cudaEventDisableTiming);
        cudaEventCreateWithFlags(&evA, cudaEventDisableTiming);
        cudaEventCreateWithFlags(&evB, cudaEventDisableTiming);
        cudaEventCreateWithFlags(&evC, cudaEventDisableTiming);
    }

    // fork s1 (routing path)
    cudaEventRecord(ev0, 0);
    cudaStreamWaitEvent(s1, ev0, 0);
    init_kernel<<<1, 32, 0, s1>>>();
    gate_kernel<<<N_TOK, 256, 0, s1>>>(x, gw, gb);
    scanscatter_kernel<<<1, 1024, 0, s1>>>();
    cudaEventRecord(evA, s1);

    // default: convert w1 (critical path head)
    cvtw_kernel<<<4096, 256>>>(w1, w1h);
    cudaEventRecord(evC, 0);

    // s2: convert w2, concurrent with ffn1
    cudaStreamWaitEvent(s2, evC, 0);
    cvtw_kernel<<<4096, 256, 0, s2>>>(w2, w2h);
    cudaEventRecord(evB, s2);

    // default: ffn1 after routing + w1h
    cudaStreamWaitEvent(0, evA, 0);
    ffn_kernel<DMODEL, HDIM, 1><<<dim3(HDIM / TILE_N, MAX_TILES), 256, SMEM_DYN>>>(w1h, b1);

    // default: ffn2 after ffn1 + w2h
    cudaStreamWaitEvent(0, evB, 0);
    ffn_kernel<HDIM, DMODEL, 2><<<dim3(DMODEL / TILE_N, MAX_TILES), 256, SMEM_DYN>>>(w2h, b2);

    ln_kernel<<<N_TOK, 256>>>(x, lnw, lnb, out);
}